// round 14
// baseline (speedup 1.0000x reference)
#include <cuda_runtime.h>
#include <cstdint>

#define BATCH    256
#define IN_CAPS  1152
#define NUM_CAPS 10
#define DIM_VEC  16
#define ITILE    16
#define NBLK_I   (IN_CAPS / ITILE)    // 72
#define B_TILE   32
#define NBLK_B   (BATCH / B_TILE)     // 8
#define NTH      (B_TILE * NUM_CAPS)  // 320
#define NBLOCKS  (NBLK_I * NBLK_B)    // 576
#define EPS 1e-7f

// Shared carve-up (floats)
#define WS_F   (ITILE * NUM_CAPS * 8 * DIM_VEC)  // 20480 : [ii][c][e][d16]
#define XS_F   (B_TILE * 132)                    // 4224  : [bb][j] stride 132
#define EX_F   (4 * B_TILE * 11)                 // 1408  : [slot][bb][c] stride 11
#define CF_F   (ITILE * NUM_CAPS)                // 160   : coef0 tile (pass0)
#define SMEM_BYTES ((WS_F + XS_F + EX_F + CF_F) * 4)   // 105088 B

__device__ float g_sbuf[3][BATCH * NUM_CAPS * DIM_VEC];   // zero-init; pass2 epilogue re-zeros
__device__ float g_blog[IN_CAPS * NUM_CAPS * BATCH];      // [i][c][b] : stores b1+bias
__device__ unsigned int g_ticket;                         // zero-init; reset each replay

using ull = unsigned long long;
__device__ __forceinline__ ull pack2(float lo, float hi) {
    ull r; asm("mov.b64 %0,{%1,%2};" : "=l"(r) : "f"(lo), "f"(hi)); return r;
}
__device__ __forceinline__ ull dup2(float v) {
    ull r; asm("mov.b64 %0,{%1,%1};" : "=l"(r) : "f"(v)); return r;
}
__device__ __forceinline__ void unpack2(ull v, float& lo, float& hi) {
    asm("mov.b64 {%0,%1},%2;" : "=f"(lo), "=f"(hi) : "l"(v));
}
__device__ __forceinline__ ull ffma2(ull a, ull b, ull c) {
    ull d; asm("fma.rn.f32x2 %0,%1,%2,%3;" : "=l"(d) : "l"(a), "l"(b), "l"(c)); return d;
}

// PASS 0: s0 += softmax_c(bias) * u_hat            (no in-loop barriers/exchange)
// PASS 1: v1=squash(s0); b1 = uh.v1 + 2*bias; blog=b1+bias; s1 += softmax(b1)*u_hat
// PASS 2: v2=squash(s1); b2 = uh.v2 + blog;                 s2 += softmax(b2)*u_hat
//         + last-block epilogue: out = squash(s2); zero scratch; reset ticket
template <int PASS>
__global__ void __launch_bounds__(NTH, 2)
pass_kernel(const float* __restrict__ x,     // [256,1152,8]
            const float* __restrict__ W,     // [1152,10,16,8]
            const float* __restrict__ bias,  // [1152,10]
            float* __restrict__ out)         // [256,10,16] (used by PASS 2 only)
{
    extern __shared__ __align__(16) float sh[];
    float* ws  = sh;                          // W tile [ii][c][e][d16]
    float* xs  = sh + WS_F;                   // x tile [bb][j] stride 132
    float* exs = sh + WS_F + XS_F;            // exchange [4][bb][c] stride 11
    float* cfs = exs + EX_F;                  // coef0 tile [ii][c] (pass0 only)
    __shared__ unsigned int tkt;

    const int tid = threadIdx.x;
    const int bb  = tid & 31;                 // lane = batch in tile
    const int c   = tid >> 5;                 // warp = capsule
    const int i0  = blockIdx.x * ITILE;
    const int b0  = blockIdx.y * B_TILE;
    const int b   = b0 + bb;

    // ---- Stage W tile: global [i][c][d][e] (float4 = d,e0..3) -> ws[ii][c][e][d]
    {
        const float4* Wg = (const float4*)(W + (size_t)i0 * NUM_CAPS * DIM_VEC * 8);
        #pragma unroll 2
        for (int k = tid; k < ITILE * NUM_CAPS * DIM_VEC * 2; k += NTH) {
            float4 w4 = Wg[k];                // coalesced LDG.128
            int ii = k / (NUM_CAPS * DIM_VEC * 2);
            int r  = k - ii * (NUM_CAPS * DIM_VEC * 2);
            int cc = r >> 5;
            int d  = (r >> 1) & 15;
            int e0 = (r & 1) * 4;
            float* dst = ws + (((ii * NUM_CAPS + cc) * 8) + e0) * DIM_VEC + d;
            dst[0 * DIM_VEC] = w4.x;
            dst[1 * DIM_VEC] = w4.y;
            dst[2 * DIM_VEC] = w4.z;
            dst[3 * DIM_VEC] = w4.w;
        }
    }
    // ---- Stage x tile: xs[bb][j]
    for (int t = tid; t < B_TILE * ITILE * 8; t += NTH) {
        int lb = t >> 7;
        int j  = t & 127;
        xs[lb * 132 + j] = x[(size_t)(b0 + lb) * (IN_CAPS * 8) + i0 * 8 + j];
    }
    // ---- Pass0: coef0[ii][c] = softmax_c(bias[i0+ii, :]) computed by ITILE threads
    if (PASS == 0 && tid < ITILE) {
        const float* bp = bias + (i0 + tid) * NUM_CAPS;
        float ex[NUM_CAPS]; float den = 0.f;
        #pragma unroll
        for (int k = 0; k < NUM_CAPS; k++) { ex[k] = __expf(bp[k]); den += ex[k]; }
        float inv = __frcp_rn(den);
        #pragma unroll
        for (int k = 0; k < NUM_CAPS; k++) cfs[tid * NUM_CAPS + k] = ex[k] * inv;
    }

    // PDL: our staging reads only x/W/bias -> successor may launch + stage now.
    cudaTriggerProgrammaticLaunchCompletion();

    ull vv[8];
    if (PASS > 0) {
        cudaGridDependencySynchronize();      // predecessor's s-adds must be visible
        const float4* sp = (const float4*)(g_sbuf[PASS - 1] + (b * NUM_CAPS + c) * DIM_VEC);
        float4 s4[4]; float sq = 0.f;
        #pragma unroll
        for (int q = 0; q < 4; q++) {
            s4[q] = sp[q];
            sq = fmaf(s4[q].x, s4[q].x, sq); sq = fmaf(s4[q].y, s4[q].y, sq);
            sq = fmaf(s4[q].z, s4[q].z, sq); sq = fmaf(s4[q].w, s4[q].w, sq);
        }
        float scale = sq / (1.f + sq) * rsqrtf(sq + EPS);
        #pragma unroll
        for (int q = 0; q < 4; q++) {
            vv[2 * q]     = pack2(scale * s4[q].x, scale * s4[q].y);
            vv[2 * q + 1] = pack2(scale * s4[q].z, scale * s4[q].w);
        }
    }
    __syncthreads();

    ull sacc[8];
    #pragma unroll
    for (int p = 0; p < 8; p++) sacc[p] = 0ull;

    if (PASS == 0) {
        #pragma unroll 2
        for (int ii = 0; ii < ITILE; ii++) {
            const float4* xr = (const float4*)(xs + bb * 132 + ii * 8);
            float4 xa = xr[0], xb = xr[1];
            ull x2[8];
            x2[0] = dup2(xa.x); x2[1] = dup2(xa.y); x2[2] = dup2(xa.z); x2[3] = dup2(xa.w);
            x2[4] = dup2(xb.x); x2[5] = dup2(xb.y); x2[6] = dup2(xb.z); x2[7] = dup2(xb.w);
            ull uh[8];
            #pragma unroll
            for (int p = 0; p < 8; p++) uh[p] = 0ull;
            const ulonglong2* wp = (const ulonglong2*)(ws + ((ii * NUM_CAPS + c) * 8) * DIM_VEC);
            #pragma unroll
            for (int e = 0; e < 8; e++) {
                #pragma unroll
                for (int q = 0; q < 4; q++) {
                    ulonglong2 wv = wp[e * 4 + q];
                    uh[2 * q]     = ffma2(wv.x, x2[e], uh[2 * q]);
                    uh[2 * q + 1] = ffma2(wv.y, x2[e], uh[2 * q + 1]);
                }
            }
            float coef = cfs[ii * NUM_CAPS + c];              // warp-uniform LDS
            ull cf = dup2(coef);
            #pragma unroll
            for (int p = 0; p < 8; p++) sacc[p] = ffma2(cf, uh[p], sacc[p]);
        }
        cudaGridDependencySynchronize();   // prior replay's pass2 must finish zeroing s0
    } else {
        // 2-ii pipeline, ONE barrier/pair; bias/blog prefetched at pair-top
        #pragma unroll 1
        for (int iip = 0; iip < ITILE / 2; iip++) {
            const int slot0 = (iip & 1) * 2;
            const int iA = i0 + 2 * iip;
            const int iB = iA + 1;

            float pfA, pfB;            // PASS1: bias ; PASS2: blog(=b1+bias)
            if (PASS == 1) {
                pfA = __ldg(&bias[iA * NUM_CAPS + c]);
                pfB = __ldg(&bias[iB * NUM_CAPS + c]);
            } else {
                pfA = __ldg(&g_blog[(iA * NUM_CAPS + c) * BATCH + b]);
                pfB = __ldg(&g_blog[(iB * NUM_CAPS + c) * BATCH + b]);
            }

            ull uhA[8], uhB[8];
            float exA, exB;
            #pragma unroll
            for (int sub = 0; sub < 2; sub++) {
                const int ii = 2 * iip + sub;
                const int i  = sub ? iB : iA;
                const float pf = sub ? pfB : pfA;
                ull* uh = sub ? uhB : uhA;
                const float4* xr = (const float4*)(xs + bb * 132 + ii * 8);
                float4 xa = xr[0], xb = xr[1];
                ull x2[8];
                x2[0] = dup2(xa.x); x2[1] = dup2(xa.y); x2[2] = dup2(xa.z); x2[3] = dup2(xa.w);
                x2[4] = dup2(xb.x); x2[5] = dup2(xb.y); x2[6] = dup2(xb.z); x2[7] = dup2(xb.w);
                #pragma unroll
                for (int p = 0; p < 8; p++) uh[p] = 0ull;
                const ulonglong2* wp = (const ulonglong2*)(ws + ((ii * NUM_CAPS + c) * 8) * DIM_VEC);
                #pragma unroll
                for (int e = 0; e < 8; e++) {
                    #pragma unroll
                    for (int q = 0; q < 4; q++) {
                        ulonglong2 wv = wp[e * 4 + q];
                        uh[2 * q]     = ffma2(wv.x, x2[e], uh[2 * q]);
                        uh[2 * q + 1] = ffma2(wv.y, x2[e], uh[2 * q + 1]);
                    }
                }
                ull ag0 = 0ull, ag1 = 0ull;
                #pragma unroll
                for (int p = 0; p < 4; p++) {
                    ag0 = ffma2(uh[2 * p],     vv[2 * p],     ag0);
                    ag1 = ffma2(uh[2 * p + 1], vv[2 * p + 1], ag1);
                }
                float a0, a1, a2, a3;
                unpack2(ag0, a0, a1); unpack2(ag1, a2, a3);
                float agr = (a0 + a1) + (a2 + a3);

                float bnew;
                if (PASS == 1) {
                    bnew = agr + 2.f * pf;                    // pf = bias
                    g_blog[(i * NUM_CAPS + c) * BATCH + b] = bnew + pf;  // b1+bias
                } else {
                    bnew = agr + pf;                          // pf = blog
                }
                float ex = __expf(bnew);                      // no max-subtract: bounded
                exs[((slot0 + sub) * B_TILE + bb) * 11 + c] = ex;
                if (sub == 0) exA = ex; else exB = ex;
            }
            __syncthreads();                                  // ONE barrier per 2 ii
            #pragma unroll
            for (int sub = 0; sub < 2; sub++) {
                const float* exr = exs + ((slot0 + sub) * B_TILE + bb) * 11;
                float t0 = exr[0], t1 = exr[1], t2 = exr[2], t3 = exr[3], t4 = exr[4];
                float t5 = exr[5], t6 = exr[6], t7 = exr[7], t8 = exr[8], t9 = exr[9];
                float den = ((t0 + t1) + (t2 + t3)) + ((t4 + t5) + (t6 + t7)) + (t8 + t9);
                float coef = __fdividef(sub ? exB : exA, den);
                ull cf = dup2(coef);
                const ull* uh = sub ? uhB : uhA;
                #pragma unroll
                for (int p = 0; p < 8; p++) sacc[p] = ffma2(cf, uh[p], sacc[p]);
            }
        }
    }

    // partial s[b,c,:] : 4 vectored global reductions (72 per address total)
    float* sp = g_sbuf[PASS] + (b * NUM_CAPS + c) * DIM_VEC;
    float a0, a1, a2, a3;
    #pragma unroll
    for (int q = 0; q < 4; q++) {
        unpack2(sacc[2 * q], a0, a1); unpack2(sacc[2 * q + 1], a2, a3);
        asm volatile("red.global.add.v4.f32 [%0], {%1,%2,%3,%4};"
                     :: "l"(sp + 4 * q), "f"(a0), "f"(a1), "f"(a2), "f"(a3) : "memory");
    }

    // ---- PASS 2 epilogue: last block finalizes (squash s2 -> out, zero scratch)
    if (PASS == 2) {
        __threadfence();                                     // release our red-adds
        if (tid == 0) tkt = atomicAdd(&g_ticket, 1u);
        __syncthreads();
        if (tkt == NBLOCKS - 1) {
            __threadfence();                                 // acquire all blocks' adds
            for (int t = tid; t < BATCH * NUM_CAPS; t += NTH) {
                float4* s2 = (float4*)(g_sbuf[2] + t * DIM_VEC);
                float4 s4[4]; float sq = 0.f;
                #pragma unroll
                for (int q = 0; q < 4; q++) {
                    s4[q] = s2[q];
                    sq = fmaf(s4[q].x, s4[q].x, sq); sq = fmaf(s4[q].y, s4[q].y, sq);
                    sq = fmaf(s4[q].z, s4[q].z, sq); sq = fmaf(s4[q].w, s4[q].w, sq);
                }
                float scale = sq / (1.f + sq) * rsqrtf(sq + EPS);
                float4* dst = (float4*)(out + t * DIM_VEC);
                float4 z = make_float4(0.f, 0.f, 0.f, 0.f);
                #pragma unroll
                for (int q = 0; q < 4; q++) {
                    float4 o; o.x = scale * s4[q].x; o.y = scale * s4[q].y;
                              o.z = scale * s4[q].z; o.w = scale * s4[q].w;
                    dst[q] = o;
                    s2[q] = z;
                }
            }
            float4 z = make_float4(0.f, 0.f, 0.f, 0.f);
            float4* z0 = (float4*)g_sbuf[0];
            float4* z1 = (float4*)g_sbuf[1];
            for (int t = tid; t < BATCH * NUM_CAPS * DIM_VEC / 4; t += NTH) {
                z0[t] = z; z1[t] = z;
            }
            if (tid == 0) g_ticket = 0;                      // visible at kernel boundary
        }
    }
}

extern "C" void kernel_launch(void* const* d_in, const int* in_sizes, int n_in,
                              void* d_out, int out_size)
{
    const float* x = nullptr; const float* W = nullptr; const float* bias = nullptr;
    for (int k = 0; k < n_in; k++) {
        if (in_sizes[k] == BATCH * IN_CAPS * 8)                    x    = (const float*)d_in[k];
        else if (in_sizes[k] == IN_CAPS * NUM_CAPS * DIM_VEC * 8)  W    = (const float*)d_in[k];
        else if (in_sizes[k] == IN_CAPS * NUM_CAPS)                bias = (const float*)d_in[k];
    }
    float* out = (float*)d_out;

    cudaFuncSetAttribute(pass_kernel<0>, cudaFuncAttributeMaxDynamicSharedMemorySize, SMEM_BYTES);
    cudaFuncSetAttribute(pass_kernel<1>, cudaFuncAttributeMaxDynamicSharedMemorySize, SMEM_BYTES);
    cudaFuncSetAttribute(pass_kernel<2>, cudaFuncAttributeMaxDynamicSharedMemorySize, SMEM_BYTES);

    cudaLaunchAttribute at[1];
    at[0].id = cudaLaunchAttributeProgrammaticStreamSerialization;
    at[0].val.programmaticStreamSerializationAllowed = 1;

    cudaLaunchConfig_t cfg = {};
    cfg.gridDim = dim3(NBLK_I, NBLK_B);
    cfg.blockDim = dim3(NTH, 1, 1);
    cfg.dynamicSmemBytes = SMEM_BYTES;
    cfg.stream = 0;
    cfg.attrs = at;
    cfg.numAttrs = 1;

    cudaLaunchKernelEx(&cfg, pass_kernel<0>, x, W, bias, out);
    cudaLaunchKernelEx(&cfg, pass_kernel<1>, x, W, bias, out);
    cudaLaunchKernelEx(&cfg, pass_kernel<2>, x, W, bias, out);
}

// round 15
// speedup vs baseline: 1.1793x; 1.1793x over previous
#include <cuda_runtime.h>
#include <cstdint>

#define BATCH    256
#define IN_CAPS  1152
#define NUM_CAPS 10
#define DIM_VEC  16
#define EPS 1e-7f
#define NTH      320                  // 32 lanes x 10 c-warps

// ---- pass1/2 tiling (R10 champion) ----
#define ITILE    16
#define NBLK_I   (IN_CAPS / ITILE)    // 72
#define B_TILE   32
#define NBLK_B   (BATCH / B_TILE)     // 8
#define WS_F   (ITILE * NUM_CAPS * 8 * DIM_VEC)  // 20480 : [ii][c][e][d16]
#define XS_F   (B_TILE * 132)                    // 4224  : [bb][j] stride 132
#define EX_F   (4 * B_TILE * 11)                 // 1408  : [slot][bb][c] stride 11
#define SMEM_BYTES ((WS_F + XS_F + EX_F) * 4)    // 104448 B

// ---- pass0 tiling (NB=2) ----
#define ITILE0   12
#define NBLK_I0  (IN_CAPS / ITILE0)   // 96
#define B_TILE0  64
#define NBLK_B0  (BATCH / B_TILE0)    // 4
#define XR0      100                  // x row stride (96 + 4 pad; ≡4 mod 32 -> 4-wf LDS.128)
#define WS0_F  (ITILE0 * NUM_CAPS * 8 * DIM_VEC) // 15360
#define XS0_F  (B_TILE0 * XR0)                   // 6400
#define CF0_F  (ITILE0 * NUM_CAPS)               // 120
#define SMEM0_BYTES ((WS0_F + XS0_F + CF0_F) * 4)  // 87520 B

__device__ float g_sbuf[3][BATCH * NUM_CAPS * DIM_VEC];   // zero-init; final re-zeros
__device__ float g_blog[IN_CAPS * NUM_CAPS * BATCH];      // [i][c][b] : stores b1+bias

using ull = unsigned long long;
__device__ __forceinline__ ull pack2(float lo, float hi) {
    ull r; asm("mov.b64 %0,{%1,%2};" : "=l"(r) : "f"(lo), "f"(hi)); return r;
}
__device__ __forceinline__ ull dup2(float v) {
    ull r; asm("mov.b64 %0,{%1,%1};" : "=l"(r) : "f"(v)); return r;
}
__device__ __forceinline__ void unpack2(ull v, float& lo, float& hi) {
    asm("mov.b64 {%0,%1},%2;" : "=f"(lo), "=f"(hi) : "l"(v));
}
__device__ __forceinline__ ull ffma2(ull a, ull b, ull c) {
    ull d; asm("fma.rn.f32x2 %0,%1,%2,%3;" : "=l"(d) : "l"(a), "l"(b), "l"(c)); return d;
}

// PASS 0: s0 += softmax_c(bias) * u_hat, NB=2 (coef folded into x; no uh regs)
__global__ void __launch_bounds__(NTH, 2)
pass0_kernel(const float* __restrict__ x,     // [256,1152,8]
             const float* __restrict__ W,     // [1152,10,16,8]
             const float* __restrict__ bias)  // [1152,10]
{
    extern __shared__ __align__(16) float sh[];
    float* ws  = sh;                          // W tile [ii][c][e][d16]
    float* xs  = sh + WS0_F;                  // x tile [bb64][j] stride 100
    float* cfs = sh + WS0_F + XS0_F;          // coef0 tile [ii][c]

    const int tid = threadIdx.x;
    const int bb  = tid & 31;
    const int c   = tid >> 5;
    const int i0  = blockIdx.x * ITILE0;
    const int b0  = blockIdx.y * B_TILE0;
    const int bA  = b0 + bb;
    const int bB  = bA + 32;

    // ---- Stage W tile: global [i][c][d][e] (float4 = d,e0..3) -> ws[ii][c][e][d]
    {
        const float4* Wg = (const float4*)(W + (size_t)i0 * NUM_CAPS * DIM_VEC * 8);
        #pragma unroll 2
        for (int k = tid; k < ITILE0 * NUM_CAPS * DIM_VEC * 2; k += NTH) {
            float4 w4 = Wg[k];                // coalesced LDG.128
            int ii = k / (NUM_CAPS * DIM_VEC * 2);
            int r  = k - ii * (NUM_CAPS * DIM_VEC * 2);
            int cc = r >> 5;
            int d  = (r >> 1) & 15;
            int e0 = (r & 1) * 4;
            float* dst = ws + (((ii * NUM_CAPS + cc) * 8) + e0) * DIM_VEC + d;
            dst[0 * DIM_VEC] = w4.x;
            dst[1 * DIM_VEC] = w4.y;
            dst[2 * DIM_VEC] = w4.z;
            dst[3 * DIM_VEC] = w4.w;
        }
    }
    // ---- Stage x tile: xs[bb64][j]
    for (int t = tid; t < B_TILE0 * ITILE0 * 8; t += NTH) {
        int lb = t / (ITILE0 * 8);
        int j  = t - lb * (ITILE0 * 8);
        xs[lb * XR0 + j] = x[(size_t)(b0 + lb) * (IN_CAPS * 8) + i0 * 8 + j];
    }
    // ---- coef0[ii][c] = softmax_c(bias[i0+ii, :])
    if (tid < ITILE0) {
        const float* bp = bias + (i0 + tid) * NUM_CAPS;
        float ex[NUM_CAPS]; float den = 0.f;
        #pragma unroll
        for (int k = 0; k < NUM_CAPS; k++) { ex[k] = __expf(bp[k]); den += ex[k]; }
        float inv = __frcp_rn(den);
        #pragma unroll
        for (int k = 0; k < NUM_CAPS; k++) cfs[tid * NUM_CAPS + k] = ex[k] * inv;
    }

    cudaTriggerProgrammaticLaunchCompletion();   // staging reads only x/W/bias
    __syncthreads();

    ull saccA[8], saccB[8];
    #pragma unroll
    for (int p = 0; p < 8; p++) { saccA[p] = 0ull; saccB[p] = 0ull; }

    #pragma unroll 1
    for (int ii = 0; ii < ITILE0; ii++) {
        const float cf = cfs[ii * NUM_CAPS + c];          // warp-uniform LDS
        const ulonglong2* wp = (const ulonglong2*)(ws + ((ii * NUM_CAPS + c) * 8) * DIM_VEC);

        #pragma unroll
        for (int half = 0; half < 2; half++) {
            float4 xA4 = *(const float4*)(xs + bb * XR0 + ii * 8 + half * 4);
            float4 xB4 = *(const float4*)(xs + (bb + 32) * XR0 + ii * 8 + half * 4);
            float xvA[4] = {xA4.x * cf, xA4.y * cf, xA4.z * cf, xA4.w * cf};
            float xvB[4] = {xB4.x * cf, xB4.y * cf, xB4.z * cf, xB4.w * cf};
            #pragma unroll
            for (int e = 0; e < 4; e++) {
                const ulonglong2* wq = wp + (half * 4 + e) * 4;
                ulonglong2 w0 = wq[0];
                ulonglong2 w1 = wq[1];
                ull xA = dup2(xvA[e]);
                ull xB = dup2(xvB[e]);
                saccA[0] = ffma2(w0.x, xA, saccA[0]);
                saccA[1] = ffma2(w0.y, xA, saccA[1]);
                saccA[2] = ffma2(w1.x, xA, saccA[2]);
                saccA[3] = ffma2(w1.y, xA, saccA[3]);
                saccB[0] = ffma2(w0.x, xB, saccB[0]);
                saccB[1] = ffma2(w0.y, xB, saccB[1]);
                saccB[2] = ffma2(w1.x, xB, saccB[2]);
                saccB[3] = ffma2(w1.y, xB, saccB[3]);
                ulonglong2 w2 = wq[2];
                ulonglong2 w3 = wq[3];
                saccA[4] = ffma2(w2.x, xA, saccA[4]);
                saccA[5] = ffma2(w2.y, xA, saccA[5]);
                saccA[6] = ffma2(w3.x, xA, saccA[6]);
                saccA[7] = ffma2(w3.y, xA, saccA[7]);
                saccB[4] = ffma2(w2.x, xB, saccB[4]);
                saccB[5] = ffma2(w2.y, xB, saccB[5]);
                saccB[6] = ffma2(w3.x, xB, saccB[6]);
                saccB[7] = ffma2(w3.y, xB, saccB[7]);
            }
        }
    }

    cudaGridDependencySynchronize();   // prior replay's final must finish zeroing s0
    float a0, a1, a2, a3;
    float* spA = g_sbuf[0] + (bA * NUM_CAPS + c) * DIM_VEC;
    float* spB = g_sbuf[0] + (bB * NUM_CAPS + c) * DIM_VEC;
    #pragma unroll
    for (int q = 0; q < 4; q++) {
        unpack2(saccA[2 * q], a0, a1); unpack2(saccA[2 * q + 1], a2, a3);
        asm volatile("red.global.add.v4.f32 [%0], {%1,%2,%3,%4};"
                     :: "l"(spA + 4 * q), "f"(a0), "f"(a1), "f"(a2), "f"(a3) : "memory");
        unpack2(saccB[2 * q], a0, a1); unpack2(saccB[2 * q + 1], a2, a3);
        asm volatile("red.global.add.v4.f32 [%0], {%1,%2,%3,%4};"
                     :: "l"(spB + 4 * q), "f"(a0), "f"(a1), "f"(a2), "f"(a3) : "memory");
    }
}

// PASS 1: v1=squash(s0); b1 = uh.v1 + 2*bias; blog=b1+bias; s1 += softmax(b1)*u_hat
// PASS 2: v2=squash(s1); b2 = uh.v2 + blog;                 s2 += softmax(b2)*u_hat
template <int PASS>
__global__ void __launch_bounds__(NTH, 2)
pass_kernel(const float* __restrict__ x,     // [256,1152,8]
            const float* __restrict__ W,     // [1152,10,16,8]
            const float* __restrict__ bias)  // [1152,10]
{
    extern __shared__ __align__(16) float sh[];
    float* ws  = sh;                          // W tile [ii][c][e][d16]
    float* xs  = sh + WS_F;                   // x tile [bb][j] stride 132
    float* exs = sh + WS_F + XS_F;            // exchange [4][bb][c] stride 11

    const int tid = threadIdx.x;
    const int bb  = tid & 31;
    const int c   = tid >> 5;
    const int i0  = blockIdx.x * ITILE;
    const int b0  = blockIdx.y * B_TILE;
    const int b   = b0 + bb;

    {
        const float4* Wg = (const float4*)(W + (size_t)i0 * NUM_CAPS * DIM_VEC * 8);
        #pragma unroll 2
        for (int k = tid; k < ITILE * NUM_CAPS * DIM_VEC * 2; k += NTH) {
            float4 w4 = Wg[k];
            int ii = k / (NUM_CAPS * DIM_VEC * 2);
            int r  = k - ii * (NUM_CAPS * DIM_VEC * 2);
            int cc = r >> 5;
            int d  = (r >> 1) & 15;
            int e0 = (r & 1) * 4;
            float* dst = ws + (((ii * NUM_CAPS + cc) * 8) + e0) * DIM_VEC + d;
            dst[0 * DIM_VEC] = w4.x;
            dst[1 * DIM_VEC] = w4.y;
            dst[2 * DIM_VEC] = w4.z;
            dst[3 * DIM_VEC] = w4.w;
        }
    }
    for (int t = tid; t < B_TILE * ITILE * 8; t += NTH) {
        int lb = t >> 7;
        int j  = t & 127;
        xs[lb * 132 + j] = x[(size_t)(b0 + lb) * (IN_CAPS * 8) + i0 * 8 + j];
    }

    cudaTriggerProgrammaticLaunchCompletion();

    ull vv[8];
    {
        cudaGridDependencySynchronize();      // predecessor's s-adds visible
        const float4* sp = (const float4*)(g_sbuf[PASS - 1] + (b * NUM_CAPS + c) * DIM_VEC);
        float4 s4[4]; float sq = 0.f;
        #pragma unroll
        for (int q = 0; q < 4; q++) {
            s4[q] = sp[q];
            sq = fmaf(s4[q].x, s4[q].x, sq); sq = fmaf(s4[q].y, s4[q].y, sq);
            sq = fmaf(s4[q].z, s4[q].z, sq); sq = fmaf(s4[q].w, s4[q].w, sq);
        }
        float scale = sq / (1.f + sq) * rsqrtf(sq + EPS);
        #pragma unroll
        for (int q = 0; q < 4; q++) {
            vv[2 * q]     = pack2(scale * s4[q].x, scale * s4[q].y);
            vv[2 * q + 1] = pack2(scale * s4[q].z, scale * s4[q].w);
        }
    }
    __syncthreads();

    ull sacc[8];
    #pragma unroll
    for (int p = 0; p < 8; p++) sacc[p] = 0ull;

    #pragma unroll 1
    for (int iip = 0; iip < ITILE / 2; iip++) {
        const int slot0 = (iip & 1) * 2;
        const int iA = i0 + 2 * iip;
        const int iB = iA + 1;

        float pfA, pfB;            // PASS1: bias ; PASS2: blog(=b1+bias)
        if (PASS == 1) {
            pfA = __ldg(&bias[iA * NUM_CAPS + c]);
            pfB = __ldg(&bias[iB * NUM_CAPS + c]);
        } else {
            pfA = __ldg(&g_blog[(iA * NUM_CAPS + c) * BATCH + b]);
            pfB = __ldg(&g_blog[(iB * NUM_CAPS + c) * BATCH + b]);
        }

        ull uhA[8], uhB[8];
        float exA, exB;
        #pragma unroll
        for (int sub = 0; sub < 2; sub++) {
            const int ii = 2 * iip + sub;
            const int i  = sub ? iB : iA;
            const float pf = sub ? pfB : pfA;
            ull* uh = sub ? uhB : uhA;
            const float4* xr = (const float4*)(xs + bb * 132 + ii * 8);
            float4 xa = xr[0], xb = xr[1];
            ull x2[8];
            x2[0] = dup2(xa.x); x2[1] = dup2(xa.y); x2[2] = dup2(xa.z); x2[3] = dup2(xa.w);
            x2[4] = dup2(xb.x); x2[5] = dup2(xb.y); x2[6] = dup2(xb.z); x2[7] = dup2(xb.w);
            #pragma unroll
            for (int p = 0; p < 8; p++) uh[p] = 0ull;
            const ulonglong2* wp = (const ulonglong2*)(ws + ((ii * NUM_CAPS + c) * 8) * DIM_VEC);
            #pragma unroll
            for (int e = 0; e < 8; e++) {
                #pragma unroll
                for (int q = 0; q < 4; q++) {
                    ulonglong2 wv = wp[e * 4 + q];
                    uh[2 * q]     = ffma2(wv.x, x2[e], uh[2 * q]);
                    uh[2 * q + 1] = ffma2(wv.y, x2[e], uh[2 * q + 1]);
                }
            }
            ull ag0 = 0ull, ag1 = 0ull;
            #pragma unroll
            for (int p = 0; p < 4; p++) {
                ag0 = ffma2(uh[2 * p],     vv[2 * p],     ag0);
                ag1 = ffma2(uh[2 * p + 1], vv[2 * p + 1], ag1);
            }
            float a0, a1, a2, a3;
            unpack2(ag0, a0, a1); unpack2(ag1, a2, a3);
            float agr = (a0 + a1) + (a2 + a3);

            float bnew;
            if (PASS == 1) {
                bnew = agr + 2.f * pf;
                g_blog[(i * NUM_CAPS + c) * BATCH + b] = bnew + pf;  // b1+bias
            } else {
                bnew = agr + pf;
            }
            float ex = __expf(bnew);                      // no max-subtract: bounded
            exs[((slot0 + sub) * B_TILE + bb) * 11 + c] = ex;
            if (sub == 0) exA = ex; else exB = ex;
        }
        __syncthreads();                                  // ONE barrier per 2 ii
        #pragma unroll
        for (int sub = 0; sub < 2; sub++) {
            const float* exr = exs + ((slot0 + sub) * B_TILE + bb) * 11;
            float t0 = exr[0], t1 = exr[1], t2 = exr[2], t3 = exr[3], t4 = exr[4];
            float t5 = exr[5], t6 = exr[6], t7 = exr[7], t8 = exr[8], t9 = exr[9];
            float den = ((t0 + t1) + (t2 + t3)) + ((t4 + t5) + (t6 + t7)) + (t8 + t9);
            float coef = __fdividef(sub ? exB : exA, den);
            ull cf = dup2(coef);
            const ull* uh = sub ? uhB : uhA;
            #pragma unroll
            for (int p = 0; p < 8; p++) sacc[p] = ffma2(cf, uh[p], sacc[p]);
        }
    }

    float* sp = g_sbuf[PASS] + (b * NUM_CAPS + c) * DIM_VEC;
    float a0, a1, a2, a3;
    #pragma unroll
    for (int q = 0; q < 4; q++) {
        unpack2(sacc[2 * q], a0, a1); unpack2(sacc[2 * q + 1], a2, a3);
        asm volatile("red.global.add.v4.f32 [%0], {%1,%2,%3,%4};"
                     :: "l"(sp + 4 * q), "f"(a0), "f"(a1), "f"(a2), "f"(a3) : "memory");
    }
}

// out = squash(s2); re-zero all scratch for graph-replay determinism
__global__ void final_kernel(float* __restrict__ out)
{
    cudaTriggerProgrammaticLaunchCompletion();   // let next replay's pass0 stage early
    cudaGridDependencySynchronize();             // pass2 complete before we read/zero
    int t = blockIdx.x * blockDim.x + threadIdx.x;
    if (t < BATCH * NUM_CAPS) {
        float4* sp = (float4*)(g_sbuf[2] + t * DIM_VEC);
        float4 s4[4]; float sq = 0.f;
        #pragma unroll
        for (int q = 0; q < 4; q++) {
            s4[q] = sp[q];
            sq = fmaf(s4[q].x, s4[q].x, sq); sq = fmaf(s4[q].y, s4[q].y, sq);
            sq = fmaf(s4[q].z, s4[q].z, sq); sq = fmaf(s4[q].w, s4[q].w, sq);
        }
        float scale = sq / (1.f + sq) * rsqrtf(sq + EPS);
        float4* dst = (float4*)(out + t * DIM_VEC);
        float4 z = make_float4(0.f, 0.f, 0.f, 0.f);
        #pragma unroll
        for (int q = 0; q < 4; q++) {
            float4 o; o.x = scale * s4[q].x; o.y = scale * s4[q].y;
                      o.z = scale * s4[q].z; o.w = scale * s4[q].w;
            dst[q] = o;
            sp[q] = z;
        }
    }
    if (t < BATCH * NUM_CAPS * DIM_VEC) {
        g_sbuf[0][t] = 0.f;
        g_sbuf[1][t] = 0.f;
    }
}

extern "C" void kernel_launch(void* const* d_in, const int* in_sizes, int n_in,
                              void* d_out, int out_size)
{
    const float* x = nullptr; const float* W = nullptr; const float* bias = nullptr;
    for (int k = 0; k < n_in; k++) {
        if (in_sizes[k] == BATCH * IN_CAPS * 8)                    x    = (const float*)d_in[k];
        else if (in_sizes[k] == IN_CAPS * NUM_CAPS * DIM_VEC * 8)  W    = (const float*)d_in[k];
        else if (in_sizes[k] == IN_CAPS * NUM_CAPS)                bias = (const float*)d_in[k];
    }
    float* out = (float*)d_out;

    cudaFuncSetAttribute(pass0_kernel,   cudaFuncAttributeMaxDynamicSharedMemorySize, SMEM0_BYTES);
    cudaFuncSetAttribute(pass_kernel<1>, cudaFuncAttributeMaxDynamicSharedMemorySize, SMEM_BYTES);
    cudaFuncSetAttribute(pass_kernel<2>, cudaFuncAttributeMaxDynamicSharedMemorySize, SMEM_BYTES);

    cudaLaunchAttribute at[1];
    at[0].id = cudaLaunchAttributeProgrammaticStreamSerialization;
    at[0].val.programmaticStreamSerializationAllowed = 1;

    cudaLaunchConfig_t c0 = {};
    c0.gridDim = dim3(NBLK_I0, NBLK_B0);
    c0.blockDim = dim3(NTH, 1, 1);
    c0.dynamicSmemBytes = SMEM0_BYTES;
    c0.stream = 0;
    c0.attrs = at;
    c0.numAttrs = 1;
    cudaLaunchKernelEx(&c0, pass0_kernel, x, W, bias);

    cudaLaunchConfig_t cfg = {};
    cfg.gridDim = dim3(NBLK_I, NBLK_B);
    cfg.blockDim = dim3(NTH, 1, 1);
    cfg.dynamicSmemBytes = SMEM_BYTES;
    cfg.stream = 0;
    cfg.attrs = at;
    cfg.numAttrs = 1;
    cudaLaunchKernelEx(&cfg, pass_kernel<1>, x, W, bias);
    cudaLaunchKernelEx(&cfg, pass_kernel<2>, x, W, bias);

    cudaLaunchConfig_t fcfg = {};
    fcfg.gridDim = dim3((BATCH * NUM_CAPS * DIM_VEC + 255) / 256, 1, 1);
    fcfg.blockDim = dim3(256, 1, 1);
    fcfg.dynamicSmemBytes = 0;
    fcfg.stream = 0;
    fcfg.attrs = at;
    fcfg.numAttrs = 1;
    cudaLaunchKernelEx(&fcfg, final_kernel, out);
}

// round 16
// speedup vs baseline: 1.2258x; 1.0394x over previous
#include <cuda_runtime.h>
#include <cstdint>

#define BATCH    256
#define IN_CAPS  1152
#define NUM_CAPS 10
#define DIM_VEC  16
#define EPS 1e-7f
#define NTH      320                  // 32 lanes x 10 c-warps

// ---- pass1/2 tiling (champion) ----
#define ITILE    16
#define NBLK_I   (IN_CAPS / ITILE)    // 72
#define B_TILE   32
#define NBLK_B   (BATCH / B_TILE)     // 8
#define WS_F   (ITILE * NUM_CAPS * 8 * DIM_VEC)  // 20480 : [ii][c][e][d16]
#define XS_F   (B_TILE * 132)                    // 4224  : [bb][j] stride 132
#define EX_F   (4 * B_TILE * 11)                 // 1408  : [slot][bb][c] stride 11
#define SMEM_BYTES ((WS_F + XS_F + EX_F) * 4)    // 104448 B

// ---- pass0 tiling (NB=4) ----
#define ITILE0   8
#define NBLK_I0  (IN_CAPS / ITILE0)   // 144
#define B_TILE0  128
#define NBLK_B0  (BATCH / B_TILE0)    // 2
#define XR0      68                   // x row stride (64 + 4 pad; ≡4 mod 32 -> conflict-free)
#define WS0_F  (ITILE0 * NUM_CAPS * 8 * DIM_VEC) // 10240
#define XS0_F  (B_TILE0 * XR0)                   // 8704
#define CF0_F  (ITILE0 * NUM_CAPS)               // 80
#define SMEM0_BYTES ((WS0_F + XS0_F + CF0_F) * 4)  // 76096 B

__device__ float g_sbuf[3][BATCH * NUM_CAPS * DIM_VEC];   // zero-init; final re-zeros
__device__ float g_blog[IN_CAPS * NUM_CAPS * BATCH];      // [i][c][b] : stores b1+bias

using ull = unsigned long long;
__device__ __forceinline__ ull pack2(float lo, float hi) {
    ull r; asm("mov.b64 %0,{%1,%2};" : "=l"(r) : "f"(lo), "f"(hi)); return r;
}
__device__ __forceinline__ ull dup2(float v) {
    ull r; asm("mov.b64 %0,{%1,%1};" : "=l"(r) : "f"(v)); return r;
}
__device__ __forceinline__ void unpack2(ull v, float& lo, float& hi) {
    asm("mov.b64 {%0,%1},%2;" : "=f"(lo), "=f"(hi) : "l"(v));
}
__device__ __forceinline__ ull ffma2(ull a, ull b, ull c) {
    ull d; asm("fma.rn.f32x2 %0,%1,%2,%3;" : "=l"(d) : "l"(a), "l"(b), "l"(c)); return d;
}

// PASS 0: s0 += softmax_c(bias) * u_hat, NB=4 (coef folded into x; no uh regs)
__global__ void __launch_bounds__(NTH, 2)
pass0_kernel(const float* __restrict__ x,     // [256,1152,8]
             const float* __restrict__ W,     // [1152,10,16,8]
             const float* __restrict__ bias)  // [1152,10]
{
    extern __shared__ __align__(16) float sh[];
    float* ws  = sh;                          // W tile [ii][c][e][d16]
    float* xs  = sh + WS0_F;                  // x tile [bb128][j] stride 68
    float* cfs = sh + WS0_F + XS0_F;          // coef0 tile [ii][c]

    const int tid = threadIdx.x;
    const int bb  = tid & 31;
    const int c   = tid >> 5;
    const int i0  = blockIdx.x * ITILE0;
    const int b0  = blockIdx.y * B_TILE0;

    // ---- Stage W tile: global [i][c][d][e] (float4 = d,e0..3) -> ws[ii][c][e][d]
    {
        const float4* Wg = (const float4*)(W + (size_t)i0 * NUM_CAPS * DIM_VEC * 8);
        #pragma unroll 2
        for (int k = tid; k < ITILE0 * NUM_CAPS * DIM_VEC * 2; k += NTH) {
            float4 w4 = Wg[k];                // coalesced LDG.128
            int ii = k / (NUM_CAPS * DIM_VEC * 2);
            int r  = k - ii * (NUM_CAPS * DIM_VEC * 2);
            int cc = r >> 5;
            int d  = (r >> 1) & 15;
            int e0 = (r & 1) * 4;
            float* dst = ws + (((ii * NUM_CAPS + cc) * 8) + e0) * DIM_VEC + d;
            dst[0 * DIM_VEC] = w4.x;
            dst[1 * DIM_VEC] = w4.y;
            dst[2 * DIM_VEC] = w4.z;
            dst[3 * DIM_VEC] = w4.w;
        }
    }
    // ---- Stage x tile: xs[bb128][j]
    for (int t = tid; t < B_TILE0 * ITILE0 * 8; t += NTH) {
        int lb = t >> 6;                       // /64
        int j  = t & 63;
        xs[lb * XR0 + j] = x[(size_t)(b0 + lb) * (IN_CAPS * 8) + i0 * 8 + j];
    }
    // ---- coef0[ii][c] = softmax_c(bias[i0+ii, :])
    if (tid < ITILE0) {
        const float* bp = bias + (i0 + tid) * NUM_CAPS;
        float ex[NUM_CAPS]; float den = 0.f;
        #pragma unroll
        for (int k = 0; k < NUM_CAPS; k++) { ex[k] = __expf(bp[k]); den += ex[k]; }
        float inv = __frcp_rn(den);
        #pragma unroll
        for (int k = 0; k < NUM_CAPS; k++) cfs[tid * NUM_CAPS + k] = ex[k] * inv;
    }

    cudaTriggerProgrammaticLaunchCompletion();   // staging reads only x/W/bias
    __syncthreads();

    ull sacc[4][8];
    #pragma unroll
    for (int nb = 0; nb < 4; nb++)
        #pragma unroll
        for (int p = 0; p < 8; p++) sacc[nb][p] = 0ull;

    #pragma unroll 1
    for (int ii = 0; ii < ITILE0; ii++) {
        const float cf = cfs[ii * NUM_CAPS + c];          // warp-uniform LDS
        const ulonglong2* wp = (const ulonglong2*)(ws + ((ii * NUM_CAPS + c) * 8) * DIM_VEC);

        #pragma unroll
        for (int half = 0; half < 2; half++) {
            float xv[4][4];
            #pragma unroll
            for (int nb = 0; nb < 4; nb++) {
                float4 x4 = *(const float4*)(xs + (bb + 32 * nb) * XR0 + ii * 8 + half * 4);
                xv[nb][0] = x4.x * cf; xv[nb][1] = x4.y * cf;
                xv[nb][2] = x4.z * cf; xv[nb][3] = x4.w * cf;
            }
            #pragma unroll
            for (int e = 0; e < 4; e++) {
                const ulonglong2* wq = wp + (half * 4 + e) * 4;
                ulonglong2 w0 = wq[0];
                ulonglong2 w1 = wq[1];
                ulonglong2 w2 = wq[2];
                ulonglong2 w3 = wq[3];
                #pragma unroll
                for (int nb = 0; nb < 4; nb++) {
                    ull xd = dup2(xv[nb][e]);
                    sacc[nb][0] = ffma2(w0.x, xd, sacc[nb][0]);
                    sacc[nb][1] = ffma2(w0.y, xd, sacc[nb][1]);
                    sacc[nb][2] = ffma2(w1.x, xd, sacc[nb][2]);
                    sacc[nb][3] = ffma2(w1.y, xd, sacc[nb][3]);
                    sacc[nb][4] = ffma2(w2.x, xd, sacc[nb][4]);
                    sacc[nb][5] = ffma2(w2.y, xd, sacc[nb][5]);
                    sacc[nb][6] = ffma2(w3.x, xd, sacc[nb][6]);
                    sacc[nb][7] = ffma2(w3.y, xd, sacc[nb][7]);
                }
            }
        }
    }

    cudaGridDependencySynchronize();   // prior replay's final must finish zeroing s0
    float a0, a1, a2, a3;
    #pragma unroll
    for (int nb = 0; nb < 4; nb++) {
        float* sp = g_sbuf[0] + ((b0 + bb + 32 * nb) * NUM_CAPS + c) * DIM_VEC;
        #pragma unroll
        for (int q = 0; q < 4; q++) {
            unpack2(sacc[nb][2 * q], a0, a1); unpack2(sacc[nb][2 * q + 1], a2, a3);
            asm volatile("red.global.add.v4.f32 [%0], {%1,%2,%3,%4};"
                         :: "l"(sp + 4 * q), "f"(a0), "f"(a1), "f"(a2), "f"(a3) : "memory");
        }
    }
}

// PASS 1: v1=squash(s0); b1 = uh.v1 + 2*bias; blog=b1+bias; s1 += softmax(b1)*u_hat
// PASS 2: v2=squash(s1); b2 = uh.v2 + blog;                 s2 += softmax(b2)*u_hat
template <int PASS>
__global__ void __launch_bounds__(NTH, 2)
pass_kernel(const float* __restrict__ x,     // [256,1152,8]
            const float* __restrict__ W,     // [1152,10,16,8]
            const float* __restrict__ bias)  // [1152,10]
{
    extern __shared__ __align__(16) float sh[];
    float* ws  = sh;                          // W tile [ii][c][e][d16]
    float* xs  = sh + WS_F;                   // x tile [bb][j] stride 132
    float* exs = sh + WS_F + XS_F;            // exchange [4][bb][c] stride 11

    const int tid = threadIdx.x;
    const int bb  = tid & 31;
    const int c   = tid >> 5;
    const int i0  = blockIdx.x * ITILE;
    const int b0  = blockIdx.y * B_TILE;
    const int b   = b0 + bb;

    {
        const float4* Wg = (const float4*)(W + (size_t)i0 * NUM_CAPS * DIM_VEC * 8);
        #pragma unroll 2
        for (int k = tid; k < ITILE * NUM_CAPS * DIM_VEC * 2; k += NTH) {
            float4 w4 = Wg[k];
            int ii = k / (NUM_CAPS * DIM_VEC * 2);
            int r  = k - ii * (NUM_CAPS * DIM_VEC * 2);
            int cc = r >> 5;
            int d  = (r >> 1) & 15;
            int e0 = (r & 1) * 4;
            float* dst = ws + (((ii * NUM_CAPS + cc) * 8) + e0) * DIM_VEC + d;
            dst[0 * DIM_VEC] = w4.x;
            dst[1 * DIM_VEC] = w4.y;
            dst[2 * DIM_VEC] = w4.z;
            dst[3 * DIM_VEC] = w4.w;
        }
    }
    for (int t = tid; t < B_TILE * ITILE * 8; t += NTH) {
        int lb = t >> 7;
        int j  = t & 127;
        xs[lb * 132 + j] = x[(size_t)(b0 + lb) * (IN_CAPS * 8) + i0 * 8 + j];
    }

    cudaTriggerProgrammaticLaunchCompletion();

    ull vv[8];
    {
        cudaGridDependencySynchronize();      // predecessor's s-adds visible
        const float4* sp = (const float4*)(g_sbuf[PASS - 1] + (b * NUM_CAPS + c) * DIM_VEC);
        float4 s4[4]; float sq = 0.f;
        #pragma unroll
        for (int q = 0; q < 4; q++) {
            s4[q] = sp[q];
            sq = fmaf(s4[q].x, s4[q].x, sq); sq = fmaf(s4[q].y, s4[q].y, sq);
            sq = fmaf(s4[q].z, s4[q].z, sq); sq = fmaf(s4[q].w, s4[q].w, sq);
        }
        float scale = sq / (1.f + sq) * rsqrtf(sq + EPS);
        #pragma unroll
        for (int q = 0; q < 4; q++) {
            vv[2 * q]     = pack2(scale * s4[q].x, scale * s4[q].y);
            vv[2 * q + 1] = pack2(scale * s4[q].z, scale * s4[q].w);
        }
    }
    __syncthreads();

    ull sacc[8];
    #pragma unroll
    for (int p = 0; p < 8; p++) sacc[p] = 0ull;

    #pragma unroll 1
    for (int iip = 0; iip < ITILE / 2; iip++) {
        const int slot0 = (iip & 1) * 2;
        const int iA = i0 + 2 * iip;
        const int iB = iA + 1;

        float pfA, pfB;            // PASS1: bias ; PASS2: blog(=b1+bias)
        if (PASS == 1) {
            pfA = __ldg(&bias[iA * NUM_CAPS + c]);
            pfB = __ldg(&bias[iB * NUM_CAPS + c]);
        } else {
            pfA = __ldg(&g_blog[(iA * NUM_CAPS + c) * BATCH + b]);
            pfB = __ldg(&g_blog[(iB * NUM_CAPS + c) * BATCH + b]);
        }

        ull uhA[8], uhB[8];
        float exA, exB;
        #pragma unroll
        for (int sub = 0; sub < 2; sub++) {
            const int ii = 2 * iip + sub;
            const int i  = sub ? iB : iA;
            const float pf = sub ? pfB : pfA;
            ull* uh = sub ? uhB : uhA;
            const float4* xr = (const float4*)(xs + bb * 132 + ii * 8);
            float4 xa = xr[0], xb = xr[1];
            ull x2[8];
            x2[0] = dup2(xa.x); x2[1] = dup2(xa.y); x2[2] = dup2(xa.z); x2[3] = dup2(xa.w);
            x2[4] = dup2(xb.x); x2[5] = dup2(xb.y); x2[6] = dup2(xb.z); x2[7] = dup2(xb.w);
            #pragma unroll
            for (int p = 0; p < 8; p++) uh[p] = 0ull;
            const ulonglong2* wp = (const ulonglong2*)(ws + ((ii * NUM_CAPS + c) * 8) * DIM_VEC);
            #pragma unroll
            for (int e = 0; e < 8; e++) {
                #pragma unroll
                for (int q = 0; q < 4; q++) {
                    ulonglong2 wv = wp[e * 4 + q];
                    uh[2 * q]     = ffma2(wv.x, x2[e], uh[2 * q]);
                    uh[2 * q + 1] = ffma2(wv.y, x2[e], uh[2 * q + 1]);
                }
            }
            ull ag0 = 0ull, ag1 = 0ull;
            #pragma unroll
            for (int p = 0; p < 4; p++) {
                ag0 = ffma2(uh[2 * p],     vv[2 * p],     ag0);
                ag1 = ffma2(uh[2 * p + 1], vv[2 * p + 1], ag1);
            }
            float a0, a1, a2, a3;
            unpack2(ag0, a0, a1); unpack2(ag1, a2, a3);
            float agr = (a0 + a1) + (a2 + a3);

            float bnew;
            if (PASS == 1) {
                bnew = agr + 2.f * pf;
                g_blog[(i * NUM_CAPS + c) * BATCH + b] = bnew + pf;  // b1+bias
            } else {
                bnew = agr + pf;
            }
            float ex = __expf(bnew);                      // no max-subtract: bounded
            exs[((slot0 + sub) * B_TILE + bb) * 11 + c] = ex;
            if (sub == 0) exA = ex; else exB = ex;
        }
        __syncthreads();                                  // ONE barrier per 2 ii
        #pragma unroll
        for (int sub = 0; sub < 2; sub++) {
            const float* exr = exs + ((slot0 + sub) * B_TILE + bb) * 11;
            float t0 = exr[0], t1 = exr[1], t2 = exr[2], t3 = exr[3], t4 = exr[4];
            float t5 = exr[5], t6 = exr[6], t7 = exr[7], t8 = exr[8], t9 = exr[9];
            float den = ((t0 + t1) + (t2 + t3)) + ((t4 + t5) + (t6 + t7)) + (t8 + t9);
            float coef = __fdividef(sub ? exB : exA, den);
            ull cf = dup2(coef);
            const ull* uh = sub ? uhB : uhA;
            #pragma unroll
            for (int p = 0; p < 8; p++) sacc[p] = ffma2(cf, uh[p], sacc[p]);
        }
    }

    float* sp = g_sbuf[PASS] + (b * NUM_CAPS + c) * DIM_VEC;
    float a0, a1, a2, a3;
    #pragma unroll
    for (int q = 0; q < 4; q++) {
        unpack2(sacc[2 * q], a0, a1); unpack2(sacc[2 * q + 1], a2, a3);
        asm volatile("red.global.add.v4.f32 [%0], {%1,%2,%3,%4};"
                     :: "l"(sp + 4 * q), "f"(a0), "f"(a1), "f"(a2), "f"(a3) : "memory");
    }
}

// out = squash(s2); re-zero all scratch for graph-replay determinism
__global__ void final_kernel(float* __restrict__ out)
{
    cudaTriggerProgrammaticLaunchCompletion();   // let next replay's pass0 stage early
    cudaGridDependencySynchronize();             // pass2 complete before we read/zero
    int t = blockIdx.x * blockDim.x + threadIdx.x;
    if (t < BATCH * NUM_CAPS) {
        float4* sp = (float4*)(g_sbuf[2] + t * DIM_VEC);
        float4 s4[4]; float sq = 0.f;
        #pragma unroll
        for (int q = 0; q < 4; q++) {
            s4[q] = sp[q];
            sq = fmaf(s4[q].x, s4[q].x, sq); sq = fmaf(s4[q].y, s4[q].y, sq);
            sq = fmaf(s4[q].z, s4[q].z, sq); sq = fmaf(s4[q].w, s4[q].w, sq);
        }
        float scale = sq / (1.f + sq) * rsqrtf(sq + EPS);
        float4* dst = (float4*)(out + t * DIM_VEC);
        float4 z = make_float4(0.f, 0.f, 0.f, 0.f);
        #pragma unroll
        for (int q = 0; q < 4; q++) {
            float4 o; o.x = scale * s4[q].x; o.y = scale * s4[q].y;
                      o.z = scale * s4[q].z; o.w = scale * s4[q].w;
            dst[q] = o;
            sp[q] = z;
        }
    }
    if (t < BATCH * NUM_CAPS * DIM_VEC) {
        g_sbuf[0][t] = 0.f;
        g_sbuf[1][t] = 0.f;
    }
}

extern "C" void kernel_launch(void* const* d_in, const int* in_sizes, int n_in,
                              void* d_out, int out_size)
{
    const float* x = nullptr; const float* W = nullptr; const float* bias = nullptr;
    for (int k = 0; k < n_in; k++) {
        if (in_sizes[k] == BATCH * IN_CAPS * 8)                    x    = (const float*)d_in[k];
        else if (in_sizes[k] == IN_CAPS * NUM_CAPS * DIM_VEC * 8)  W    = (const float*)d_in[k];
        else if (in_sizes[k] == IN_CAPS * NUM_CAPS)                bias = (const float*)d_in[k];
    }
    float* out = (float*)d_out;

    cudaFuncSetAttribute(pass0_kernel,   cudaFuncAttributeMaxDynamicSharedMemorySize, SMEM0_BYTES);
    cudaFuncSetAttribute(pass_kernel<1>, cudaFuncAttributeMaxDynamicSharedMemorySize, SMEM_BYTES);
    cudaFuncSetAttribute(pass_kernel<2>, cudaFuncAttributeMaxDynamicSharedMemorySize, SMEM_BYTES);

    cudaLaunchAttribute at[1];
    at[0].id = cudaLaunchAttributeProgrammaticStreamSerialization;
    at[0].val.programmaticStreamSerializationAllowed = 1;

    cudaLaunchConfig_t c0 = {};
    c0.gridDim = dim3(NBLK_I0, NBLK_B0);
    c0.blockDim = dim3(NTH, 1, 1);
    c0.dynamicSmemBytes = SMEM0_BYTES;
    c0.stream = 0;
    c0.attrs = at;
    c0.numAttrs = 1;
    cudaLaunchKernelEx(&c0, pass0_kernel, x, W, bias);

    cudaLaunchConfig_t cfg = {};
    cfg.gridDim = dim3(NBLK_I, NBLK_B);
    cfg.blockDim = dim3(NTH, 1, 1);
    cfg.dynamicSmemBytes = SMEM_BYTES;
    cfg.stream = 0;
    cfg.attrs = at;
    cfg.numAttrs = 1;
    cudaLaunchKernelEx(&cfg, pass_kernel<1>, x, W, bias);
    cudaLaunchKernelEx(&cfg, pass_kernel<2>, x, W, bias);

    cudaLaunchConfig_t fcfg = {};
    fcfg.gridDim = dim3((BATCH * NUM_CAPS * DIM_VEC + 255) / 256, 1, 1);
    fcfg.blockDim = dim3(256, 1, 1);
    fcfg.dynamicSmemBytes = 0;
    fcfg.stream = 0;
    fcfg.attrs = at;
    fcfg.numAttrs = 1;
    cudaLaunchKernelEx(&fcfg, final_kernel, out);
}